// round 10
// baseline (speedup 1.0000x reference)
#include <cuda_runtime.h>
#include <math.h>
#include <stdint.h>

#define NC 65
#define NG 22
#define MAXB 64
#define EPS 1e-8f
#define WARPS 8
#define THR_M (WARPS * 32)
#define RPW 64                 // rows per warp
#define ROWS_BLK (WARPS * RPW) // 512 rows per block
#define FULL 0xffffffffu

// ---- constants derived from AA64 = 'FFLLSSSSYY**CC*WLLLLPPPPHHQQRRRRIIIMTTTTNNKKSSRRVVVVAAAADDEEGGGG'
__constant__ int c_gid[NC] = {
    0,
    6,6, 11,11, 17,17,17,17, 21,21, 1,1, 3,3, 1, 20,
    11,11,11,11, 14,14,14,14, 8,8, 15,15, 16,16,16,16,
    9,9,9, 12, 18,18,18,18, 13,13, 10,10, 17,17, 16,16,
    19,19,19,19, 2,2,2,2, 4,4, 5,5, 7,7,7,7};
__constant__ float c_nsyn[NC] = {
    0.f,
    2,2, 6,6, 6,6,6,6, 2,2, 3,3, 2,2, 3, 1,
    6,6,6,6, 4,4,4,4, 2,2, 2,2, 6,6,6,6,
    3,3,3, 1, 4,4,4,4, 2,2, 2,2, 6,6, 6,6,
    4,4,4,4, 4,4,4,4, 2,2, 2,2, 4,4,4,4};

// ---- global scratch (zero at load; self-cleaned every run)
__device__ double g_lwp[MAXB], g_lwt[MAXB];
__device__ double g_gcs[MAXB], g_pps[MAXB];
__device__ int    g_maskc[MAXB];
__device__ int    g_cntp[MAXB][NC], g_cntt[MAXB][NC];
__device__ int    g_obsp[MAXB][NC], g_obst[MAXB][NC];
__device__ double g_ce_sum;
__device__ int    g_ce_cnt;
__device__ double g_rscu, g_cai, g_gc, g_dyn, g_str;
__device__ int    g_fin;

// ------------- Main pass: warp-per-row, no tile staging -------------
__global__ void __launch_bounds__(THR_M) mainK(
    const float* __restrict__ logits, const float* __restrict__ wmat,
    const float* __restrict__ gc,     const float* __restrict__ pause,
    const int* __restrict__ tgt,      const int* __restrict__ aa,
    const int* __restrict__ species,  const unsigned char* __restrict__ mask,
    int L)
{
    const int b    = blockIdx.y;
    const int tid  = threadIdx.x;
    const int wid  = tid >> 5, lane = tid & 31;

    __shared__ float s_logw[NC];
    __shared__ int   s_cntp[NC], s_cntt[NC], s_obsp[NC], s_obst[NC];
    __shared__ float r_ce[WARPS], r_lwp[WARPS], r_lwt[WARPS];
    __shared__ int   r_cec[WARPS], r_mk[WARPS];
    __shared__ float r_gc[WARPS], r_pp[WARPS];

    if (tid < NC) {
        int sp = species[b];
        s_logw[tid] = __logf(fmaxf(wmat[sp * NC + tid], EPS));
        s_cntp[tid] = 0; s_cntt[tid] = 0; s_obsp[tid] = 0; s_obst[tid] = 0;
    }
    __syncthreads();

    // gc / pause partial sums: this block covers ROWS_BLK elements of each
    {
        const size_t off = (size_t)b * L + (size_t)blockIdx.x * ROWS_BLK;
        const float2* gp = (const float2*)(gc    + off);
        const float2* pp = (const float2*)(pause + off);
        float2 x = gp[tid], y = pp[tid];
        float sg = x.x + x.y, sp = y.x + y.y;
        #pragma unroll
        for (int o = 16; o; o >>= 1) {
            sg += __shfl_xor_sync(FULL, sg, o);
            sp += __shfl_xor_sync(FULL, sp, o);
        }
        if (lane == 0) { r_gc[wid] = sg; r_pp[wid] = sp; }
    }

    const size_t row0 = (size_t)b * L + (size_t)blockIdx.x * ROWS_BLK + wid * RPW;

    float ce_acc = 0.f, lwp_acc = 0.f, lwt_acc = 0.f;
    int   cec_acc = 0, mk_acc = 0;

    #pragma unroll 2
    for (int i = 0; i < RPW; ++i) {
        const size_t r = row0 + i;
        const float* rp = logits + r * NC;
        float v0 = rp[lane];
        float v1 = rp[lane + 32];
        float v2 = (lane == 0) ? rp[64] : -1e30f;

        int t  = tgt[r];
        int a  = aa[r];
        int mk = mask[r];

        // warp max
        float mx = fmaxf(fmaxf(v0, v1), v2);
        #pragma unroll
        for (int o = 16; o; o >>= 1) mx = fmaxf(mx, __shfl_xor_sync(FULL, mx, o));

        // argmax, first-index tie-break
        unsigned b0 = __ballot_sync(FULL, v0 == mx);
        unsigned b1 = __ballot_sync(FULL, v1 == mx);
        int am = b0 ? (__ffs(b0) - 1) : (b1 ? (31 + __ffs(b1)) : 64);

        // sum of exps
        float e = __expf(v0 - mx) + __expf(v1 - mx) + __expf(v2 - mx);
        #pragma unroll
        for (int o = 16; o; o >>= 1) e += __shfl_xor_sync(FULL, e, o);

        // target logit (t warp-uniform)
        int ti = t & 31;
        float xa = __shfl_sync(FULL, v0, ti);
        float xb = __shfl_sync(FULL, v1, ti);
        float xc = __shfl_sync(FULL, v2, 0);
        float tl = (t < 32) ? xa : ((t < 64) ? xb : xc);

        float nll = mx + __logf(e) - tl;

        if (t != 0) { ce_acc += nll; cec_acc++; }
        if (mk) {
            mk_acc++;
            lwp_acc += s_logw[am];
            lwt_acc += s_logw[t];
            if (lane == 0) {
                if (am > 0) { atomicAdd(&s_cntp[am], 1); if (a > 2) s_obsp[am] = 1; }
                if (t  > 0) { atomicAdd(&s_cntt[t], 1);  if (a > 2) s_obst[t]  = 1; }
            }
        }
    }

    if (lane == 0) {
        r_ce[wid] = ce_acc; r_lwp[wid] = lwp_acc; r_lwt[wid] = lwt_acc;
        r_cec[wid] = cec_acc; r_mk[wid] = mk_acc;
    }
    __syncthreads();

    if (tid < NC) {
        int cp = s_cntp[tid], ct = s_cntt[tid];
        if (cp) atomicAdd(&g_cntp[b][tid], cp);
        if (ct) atomicAdd(&g_cntt[b][tid], ct);
        if (s_obsp[tid]) g_obsp[b][tid] = 1;   // idempotent
        if (s_obst[tid]) g_obst[b][tid] = 1;
    }
    if (tid == 0) {
        float ceS = 0.f, lwpS = 0.f, lwtS = 0.f, gcS = 0.f, ppS = 0.f;
        int cecS = 0, mkS = 0;
        #pragma unroll
        for (int w = 0; w < WARPS; ++w) {
            ceS += r_ce[w]; lwpS += r_lwp[w]; lwtS += r_lwt[w];
            gcS += r_gc[w]; ppS += r_pp[w];
            cecS += r_cec[w]; mkS += r_mk[w];
        }
        atomicAdd(&g_ce_sum, (double)ceS);
        atomicAdd(&g_ce_cnt, cecS);
        atomicAdd(&g_lwp[b], (double)lwpS);
        atomicAdd(&g_lwt[b], (double)lwtS);
        atomicAdd(&g_maskc[b], mkS);
        atomicAdd(&g_gcs[b], (double)gcS);
        atomicAdd(&g_pps[b], (double)ppS);
    }
}

// ------------- Tail: per-batch RSCU KL + CAI + gc/dyn/str, final combine, self-clean -------------
__global__ void __launch_bounds__(128) tailK(
    const float* __restrict__ refd, const float* __restrict__ mfe,
    const int* __restrict__ species,
    float* __restrict__ out, int B, int L)
{
    int b = blockIdx.x;
    int tid = threadIdx.x;
    __shared__ float gs_p[NG], gs_t[NG];
    __shared__ float sum_p, sum_t;
    __shared__ double kl_acc;

    if (tid < NG) { gs_p[tid] = 0.f; gs_t[tid] = 0.f; }
    if (tid == 0) { sum_p = 0.f; sum_t = 0.f; kl_acc = 0.0; }
    __syncthreads();

    int gid = 0, op = 0, ot = 0;
    float ocp = 0.f, oct = 0.f;
    if (tid < NC) {
        gid = c_gid[tid];
        bool coding = (tid != 0) && (tid != 11) && (tid != 12) && (tid != 15);
        op = g_obsp[b][tid] && coding;
        ot = g_obst[b][tid] && coding;
        ocp = op ? (float)g_cntp[b][tid] : 0.f;
        oct = ot ? (float)g_cntt[b][tid] : 0.f;
        atomicAdd(&gs_p[gid], ocp);
        atomicAdd(&gs_t[gid], oct);
    }
    __syncthreads();

    float pterm = 0.f, tterm = 0.f;
    if (tid < NC) {
        float totp = gs_p[gid], tott = gs_t[gid];
        float ns = c_nsyn[tid];
        float rp = (op && totp > 0.f) ? ocp * ns / fmaxf(totp, 1.f) : 0.f;
        float rt = (ot && tott > 0.f) ? oct * ns / fmaxf(tott, 1.f) : 0.f;
        pterm = rp + EPS;
        int sp = species[b];
        tterm = 0.7f * rt + 0.3f * refd[sp * NC + tid] + EPS;
        atomicAdd(&sum_p, pterm);
        atomicAdd(&sum_t, tterm);
    }
    __syncthreads();

    if (tid < NC) {
        double tt = (double)tterm / (double)sum_t;
        double pp = (double)pterm / (double)sum_p;
        atomicAdd(&kl_acc, tt * (log(tt) - log(pp)));
    }
    __syncthreads();

    if (tid == 0) {
        atomicAdd(&g_rscu, kl_acc);
        double denom = fmax((double)g_maskc[b], 1.0);
        double pc = exp(g_lwp[b] / denom);
        double tc = exp(g_lwt[b] / denom);
        atomicAdd(&g_cai, fmax(tc - pc, 0.0));
        double gm = g_gcs[b] / (double)L - 0.5;
        double pm = g_pps[b] / (double)L - 0.1;
        double sd = (double)mfe[b] + 20.0;
        atomicAdd(&g_gc,  gm * gm);
        atomicAdd(&g_dyn, pm * pm);
        atomicAdd(&g_str, sd * sd);
    }
    __syncthreads();

    // self-clean this batch's scratch (values already consumed above)
    if (tid < NC) {
        g_cntp[b][tid] = 0; g_cntt[b][tid] = 0;
        g_obsp[b][tid] = 0; g_obst[b][tid] = 0;
    }
    if (tid == 0) {
        g_lwp[b] = 0.0; g_lwt[b] = 0.0;
        g_gcs[b] = 0.0; g_pps[b] = 0.0;
        g_maskc[b] = 0;
    }

    // global ticket -> final combine by last block
    __threadfence();
    __shared__ int s_f;
    if (tid == 0) s_f = atomicAdd(&g_fin, 1);
    __syncthreads();
    if (s_f != B - 1) return;
    __threadfence();

    if (tid == 0) {
        double invB = 1.0 / (double)B;
        double cev = g_ce_sum / fmax((double)g_ce_cnt, 1.0);
        out[0] = (float)(cev
                       + 0.4  * g_cai  * invB
                       + 0.3  * g_rscu * invB
                       + 0.1  * g_gc   * invB
                       + 0.15 * g_str  * invB
                       + 0.1  * g_dyn  * invB);
        // reset shared scalars for next replay
        g_ce_sum = 0.0; g_ce_cnt = 0;
        g_rscu = 0.0; g_cai = 0.0; g_gc = 0.0; g_dyn = 0.0; g_str = 0.0;
        g_fin = 0;
    }
}

extern "C" void kernel_launch(void* const* d_in, const int* in_sizes, int n_in,
                              void* d_out, int out_size)
{
    const float* logits  = (const float*)d_in[0];
    const float* wmat    = (const float*)d_in[1];
    const float* refd    = (const float*)d_in[2];
    const float* gc      = (const float*)d_in[3];
    const float* mfe     = (const float*)d_in[4];
    const float* pause   = (const float*)d_in[5];
    const int*   tgt     = (const int*)d_in[6];
    const int*   aa      = (const int*)d_in[7];
    const int*   species = (const int*)d_in[8];
    const unsigned char* mask = (const unsigned char*)d_in[9];

    int B = in_sizes[4];             // mfe has B elements
    int L = in_sizes[3] / B;         // gc_pred has B*L elements

    dim3 grid(L / ROWS_BLK, B);
    mainK<<<grid, THR_M>>>(logits, wmat, gc, pause, tgt, aa, species, mask, L);
    tailK<<<B, 128>>>(refd, mfe, species, (float*)d_out, B, L);
}

// round 14
// speedup vs baseline: 2.0560x; 2.0560x over previous
#include <cuda_runtime.h>
#include <math.h>
#include <stdint.h>

#define NC 65
#define NG 22
#define MAXB 64
#define EPS 1e-8f
#define SUB 128                 // rows per subtile (one per thread)
#define NSUB 4
#define CHUNK (SUB * NSUB)      // 512 rows per block
#define THR 128
#define FULL 0xffffffffu

// ---- constants derived from AA64 = 'FFLLSSSSYY**CC*WLLLLPPPPHHQQRRRRIIIMTTTTNNKKSSRRVVVVAAAADDEEGGGG'
__constant__ int c_gid[NC] = {
    0,
    6,6, 11,11, 17,17,17,17, 21,21, 1,1, 3,3, 1, 20,
    11,11,11,11, 14,14,14,14, 8,8, 15,15, 16,16,16,16,
    9,9,9, 12, 18,18,18,18, 13,13, 10,10, 17,17, 16,16,
    19,19,19,19, 2,2,2,2, 4,4, 5,5, 7,7,7,7};
__constant__ float c_nsyn[NC] = {
    0.f,
    2,2, 6,6, 6,6,6,6, 2,2, 3,3, 2,2, 3, 1,
    6,6,6,6, 4,4,4,4, 2,2, 2,2, 6,6,6,6,
    3,3,3, 1, 4,4,4,4, 2,2, 2,2, 6,6, 6,6,
    4,4,4,4, 4,4,4,4, 2,2, 2,2, 4,4,4,4};

// ---- global scratch (zero at load; self-cleaned every run)
__device__ double g_lwp[MAXB], g_lwt[MAXB];
__device__ double g_gcs[MAXB], g_pps[MAXB];
__device__ int    g_maskc[MAXB];
__device__ int    g_cntp[MAXB][NC], g_cntt[MAXB][NC];
__device__ int    g_obsp[MAXB][NC], g_obst[MAXB][NC];
__device__ double g_ce_sum;
__device__ int    g_ce_cnt;
__device__ double g_rscu, g_cai, g_gc, g_dyn, g_str;
__device__ int    g_fin;

__device__ __forceinline__ void cp16(uint32_t saddr, const void* gptr) {
    asm volatile("cp.async.cg.shared.global [%0], [%1], 16;" :: "r"(saddr), "l"(gptr));
}
__device__ __forceinline__ void cp_commit() { asm volatile("cp.async.commit_group;"); }
template<int N> __device__ __forceinline__ void cp_wait() {
    asm volatile("cp.async.wait_group %0;" :: "n"(N));
}

// ------------- Main pass: thread-per-row, cp.async double-buffered tiles -------------
__global__ void __launch_bounds__(THR) mainK(
    const float* __restrict__ logits, const float* __restrict__ wmat,
    const float* __restrict__ gc,     const float* __restrict__ pause,
    const int* __restrict__ tgt,      const int* __restrict__ aa,
    const int* __restrict__ species,  const unsigned char* __restrict__ mask,
    int L)
{
    const int b   = blockIdx.y;
    const int tid = threadIdx.x;
    const int wid = tid >> 5, lane = tid & 31;

    extern __shared__ float smem[];
    float* s_buf  = smem;                    // 2 * SUB * NC floats (ping-pong)
    float* s_logw = smem + 2 * SUB * NC;     // NC floats

    __shared__ int   s_cntp[NC], s_cntt[NC], s_obsp[NC], s_obst[NC];
    __shared__ float r_ce[4], r_lwp[4], r_lwt[4], r_gc[4], r_pp[4];
    __shared__ int   r_cec[4], r_mk[4];

    const size_t row0 = (size_t)b * L + (size_t)blockIdx.x * CHUNK;
    const uint32_t sbase = (uint32_t)__cvta_generic_to_shared(s_buf);
    const int V = SUB * NC / 4;              // 2080 float4 per subtile

    // prefetch subtile 0
    {
        const float4* g4 = (const float4*)(logits + row0 * NC);
        for (int v = tid; v < V; v += THR) cp16(sbase + v * 16, g4 + v);
        cp_commit();
    }

    if (tid < NC) {
        int sp = __ldg(species + b);
        s_logw[tid] = __logf(fmaxf(__ldg(wmat + sp * NC + tid), EPS));
        s_cntp[tid] = 0; s_cntt[tid] = 0; s_obsp[tid] = 0; s_obst[tid] = 0;
    }

    // gc / pause partial sums: this block covers CHUNK elements of each
    {
        const float2* gp = (const float2*)(gc    + row0);
        const float2* pp = (const float2*)(pause + row0);
        float2 x0 = __ldg(gp + tid), x1 = __ldg(gp + tid + THR);
        float2 y0 = __ldg(pp + tid), y1 = __ldg(pp + tid + THR);
        float sg = x0.x + x0.y + x1.x + x1.y;
        float sp = y0.x + y0.y + y1.x + y1.y;
        #pragma unroll
        for (int o = 16; o; o >>= 1) {
            sg += __shfl_xor_sync(FULL, sg, o);
            sp += __shfl_xor_sync(FULL, sp, o);
        }
        if (lane == 0) { r_gc[wid] = sg; r_pp[wid] = sp; }
    }

    float ce_acc = 0.f, lwp_acc = 0.f, lwt_acc = 0.f;
    int   cec_acc = 0, mk_acc = 0;

    for (int s = 0; s < NSUB; ++s) {
        // prefetch next subtile into the other buffer, then drain current
        if (s + 1 < NSUB) {
            const float4* g4 = (const float4*)(logits + (row0 + (size_t)(s + 1) * SUB) * NC);
            uint32_t dst = sbase + ((s + 1) & 1) * (SUB * NC * 4);
            for (int v = tid; v < V; v += THR) cp16(dst + v * 16, g4 + v);
            cp_commit();
            cp_wait<1>();
        } else {
            cp_wait<0>();
        }
        __syncthreads();

        const float* row = s_buf + (s & 1) * (SUB * NC) + tid * NC;
        const size_t r = row0 + (size_t)s * SUB + tid;

        int t  = __ldg(tgt + r);
        int a  = __ldg(aa + r);
        int mk = __ldg(mask + r);

        // pass 1: max + argmax (strict > => first index, matches jnp.argmax)
        float mx = row[0]; int am = 0;
        #pragma unroll
        for (int c = 1; c < NC; ++c) {
            float v = row[c];
            if (v > mx) { mx = v; am = c; }
        }
        // pass 2: sum of exps (re-read smem, keeps registers low)
        float e = 0.f;
        #pragma unroll
        for (int c = 0; c < NC; ++c) e += __expf(row[c] - mx);

        float nll = mx + __logf(e) - row[t];

        if (t != 0) { ce_acc += nll; cec_acc++; }
        if (mk) {
            mk_acc++;
            lwp_acc += s_logw[am];
            lwt_acc += s_logw[t];
            if (am > 0) { atomicAdd(&s_cntp[am], 1); if (a > 2) s_obsp[am] = 1; }
            if (t  > 0) { atomicAdd(&s_cntt[t], 1);  if (a > 2) s_obst[t]  = 1; }
        }
        __syncthreads();   // done reading this buffer before it is refilled
    }

    // block reduction of scalar accumulators
    #pragma unroll
    for (int o = 16; o; o >>= 1) {
        ce_acc  += __shfl_xor_sync(FULL, ce_acc,  o);
        lwp_acc += __shfl_xor_sync(FULL, lwp_acc, o);
        lwt_acc += __shfl_xor_sync(FULL, lwt_acc, o);
        cec_acc += __shfl_xor_sync(FULL, cec_acc, o);
        mk_acc  += __shfl_xor_sync(FULL, mk_acc,  o);
    }
    if (lane == 0) {
        r_ce[wid] = ce_acc; r_lwp[wid] = lwp_acc; r_lwt[wid] = lwt_acc;
        r_cec[wid] = cec_acc; r_mk[wid] = mk_acc;
    }
    __syncthreads();

    if (tid < NC) {
        int cp = s_cntp[tid], ct = s_cntt[tid];
        if (cp) atomicAdd(&g_cntp[b][tid], cp);
        if (ct) atomicAdd(&g_cntt[b][tid], ct);
        if (s_obsp[tid]) g_obsp[b][tid] = 1;   // idempotent
        if (s_obst[tid]) g_obst[b][tid] = 1;
    }
    if (tid == 0) {
        float ceS  = r_ce[0]  + r_ce[1]  + r_ce[2]  + r_ce[3];
        float lwpS = r_lwp[0] + r_lwp[1] + r_lwp[2] + r_lwp[3];
        float lwtS = r_lwt[0] + r_lwt[1] + r_lwt[2] + r_lwt[3];
        float gcS  = r_gc[0]  + r_gc[1]  + r_gc[2]  + r_gc[3];
        float ppS  = r_pp[0]  + r_pp[1]  + r_pp[2]  + r_pp[3];
        int   cecS = r_cec[0] + r_cec[1] + r_cec[2] + r_cec[3];
        int   mkS  = r_mk[0]  + r_mk[1]  + r_mk[2]  + r_mk[3];
        atomicAdd(&g_ce_sum, (double)ceS);
        atomicAdd(&g_ce_cnt, cecS);
        atomicAdd(&g_lwp[b], (double)lwpS);
        atomicAdd(&g_lwt[b], (double)lwtS);
        atomicAdd(&g_maskc[b], mkS);
        atomicAdd(&g_gcs[b], (double)gcS);
        atomicAdd(&g_pps[b], (double)ppS);
    }
}

// ------------- Tail: per-batch RSCU KL + CAI + gc/dyn/str, final combine, self-clean -------------
__global__ void __launch_bounds__(128) tailK(
    const float* __restrict__ refd, const float* __restrict__ mfe,
    const int* __restrict__ species,
    float* __restrict__ out, int B, int L)
{
    int b = blockIdx.x;
    int tid = threadIdx.x;
    __shared__ float gs_p[NG], gs_t[NG];
    __shared__ float sum_p, sum_t;
    __shared__ float kl_acc;

    if (tid < NG) { gs_p[tid] = 0.f; gs_t[tid] = 0.f; }
    if (tid == 0) { sum_p = 0.f; sum_t = 0.f; kl_acc = 0.f; }
    __syncthreads();

    int gid = 0, op = 0, ot = 0;
    float ocp = 0.f, oct = 0.f;
    if (tid < NC) {
        gid = c_gid[tid];
        bool coding = (tid != 0) && (tid != 11) && (tid != 12) && (tid != 15);
        op = g_obsp[b][tid] && coding;
        ot = g_obst[b][tid] && coding;
        ocp = op ? (float)g_cntp[b][tid] : 0.f;
        oct = ot ? (float)g_cntt[b][tid] : 0.f;
        atomicAdd(&gs_p[gid], ocp);
        atomicAdd(&gs_t[gid], oct);
    }
    __syncthreads();

    float pterm = 0.f, tterm = 0.f;
    if (tid < NC) {
        float totp = gs_p[gid], tott = gs_t[gid];
        float ns = c_nsyn[tid];
        float rp = (op && totp > 0.f) ? ocp * ns / fmaxf(totp, 1.f) : 0.f;
        float rt = (ot && tott > 0.f) ? oct * ns / fmaxf(tott, 1.f) : 0.f;
        pterm = rp + EPS;
        int sp = species[b];
        tterm = 0.7f * rt + 0.3f * refd[sp * NC + tid] + EPS;
        atomicAdd(&sum_p, pterm);
        atomicAdd(&sum_t, tterm);
    }
    __syncthreads();

    if (tid < NC) {
        float tt = tterm / sum_t;
        float pp = pterm / sum_p;
        atomicAdd(&kl_acc, tt * (logf(tt) - logf(pp)));
    }
    __syncthreads();

    if (tid == 0) {
        atomicAdd(&g_rscu, (double)kl_acc);
        float denom = fmaxf((float)g_maskc[b], 1.f);
        float pc = expf((float)(g_lwp[b]) / denom);
        float tc = expf((float)(g_lwt[b]) / denom);
        atomicAdd(&g_cai, (double)fmaxf(tc - pc, 0.f));
        double gm = g_gcs[b] / (double)L - 0.5;
        double pm = g_pps[b] / (double)L - 0.1;
        double sd = (double)mfe[b] + 20.0;
        atomicAdd(&g_gc,  gm * gm);
        atomicAdd(&g_dyn, pm * pm);
        atomicAdd(&g_str, sd * sd);
    }
    __syncthreads();

    // self-clean this batch's scratch (values already consumed above)
    if (tid < NC) {
        g_cntp[b][tid] = 0; g_cntt[b][tid] = 0;
        g_obsp[b][tid] = 0; g_obst[b][tid] = 0;
    }
    if (tid == 0) {
        g_lwp[b] = 0.0; g_lwt[b] = 0.0;
        g_gcs[b] = 0.0; g_pps[b] = 0.0;
        g_maskc[b] = 0;
    }

    // global ticket -> final combine by last block
    __threadfence();
    __shared__ int s_f;
    if (tid == 0) s_f = atomicAdd(&g_fin, 1);
    __syncthreads();
    if (s_f != B - 1) return;
    __threadfence();

    if (tid == 0) {
        double invB = 1.0 / (double)B;
        double cev = g_ce_sum / fmax((double)g_ce_cnt, 1.0);
        out[0] = (float)(cev
                       + 0.4  * g_cai  * invB
                       + 0.3  * g_rscu * invB
                       + 0.1  * g_gc   * invB
                       + 0.15 * g_str  * invB
                       + 0.1  * g_dyn  * invB);
        // reset shared scalars for next replay
        g_ce_sum = 0.0; g_ce_cnt = 0;
        g_rscu = 0.0; g_cai = 0.0; g_gc = 0.0; g_dyn = 0.0; g_str = 0.0;
        g_fin = 0;
    }
}

extern "C" void kernel_launch(void* const* d_in, const int* in_sizes, int n_in,
                              void* d_out, int out_size)
{
    const float* logits  = (const float*)d_in[0];
    const float* wmat    = (const float*)d_in[1];
    const float* refd    = (const float*)d_in[2];
    const float* gc      = (const float*)d_in[3];
    const float* mfe     = (const float*)d_in[4];
    const float* pause   = (const float*)d_in[5];
    const int*   tgt     = (const int*)d_in[6];
    const int*   aa      = (const int*)d_in[7];
    const int*   species = (const int*)d_in[8];
    const unsigned char* mask = (const unsigned char*)d_in[9];

    int B = in_sizes[4];             // mfe has B elements
    int L = in_sizes[3] / B;         // gc_pred has B*L elements

    size_t smemM = (2 * SUB * NC + NC) * sizeof(float);   // ~67 KB
    cudaFuncSetAttribute(mainK, cudaFuncAttributeMaxDynamicSharedMemorySize, (int)smemM);

    dim3 grid(L / CHUNK, B);
    mainK<<<grid, THR, smemM>>>(logits, wmat, gc, pause, tgt, aa, species, mask, L);
    tailK<<<B, 128>>>(refd, mfe, species, (float*)d_out, B, L);
}